// round 17
// baseline (speedup 1.0000x reference)
#include <cuda_runtime.h>
#include <cuda_bf16.h>
#include <cuda_fp16.h>

#define N_TOK 4096
#define DIM   768
#define HEADS 12
#define HD    64
#define NT    (N_TOK / 128)          // 32 key tiles (128 keys) per CTA
#define HE    ((size_t)N_TOK * HD)

// ---------------------------------------------------------------------------
// Device scratch (alloc-free rule)
// ---------------------------------------------------------------------------
__device__ float  g_qkv  [(size_t)N_TOK * 3 * DIM];
__device__ __half g_xh   [(size_t)N_TOK * DIM];           // x in fp16
__device__ __half g_attnh[(size_t)N_TOK * DIM];           // attention out in fp16
__device__ __half g_Khi[HEADS * HE];                      // [h][key][hd]
__device__ __half g_Vhi[HEADS * HE];                      // [h][hd][key] (V^T)
__device__ __half g_Wqt[(size_t)3 * DIM * DIM];           // W_qkv^T [N][K] fp16
__device__ __half g_Wpt[(size_t)DIM * DIM];               // W_proj^T [N][K] fp16

// ---------------------------------------------------------------------------
// Base-target PTX helpers
// ---------------------------------------------------------------------------
__device__ __forceinline__ unsigned smem_u32(const void* p) {
    unsigned a;
    asm("{ .reg .u64 t; cvta.to.shared.u64 t, %1; cvt.u32.u64 %0, t; }" : "=r"(a) : "l"(p));
    return a;
}
__device__ __forceinline__ unsigned swz(unsigned o) { return o ^ ((o >> 3) & 0x70); }

__device__ __forceinline__ void ldmx4(unsigned& r0, unsigned& r1, unsigned& r2, unsigned& r3,
                                      unsigned addr) {
    asm volatile("ldmatrix.sync.aligned.m8n8.x4.shared.b16 {%0,%1,%2,%3}, [%4];"
                 : "=r"(r0), "=r"(r1), "=r"(r2), "=r"(r3) : "r"(addr));
}
__device__ __forceinline__ void mma16816h(float* d, const unsigned* a, unsigned b0, unsigned b1) {
    asm volatile("mma.sync.aligned.m16n8k16.row.col.f32.f16.f16.f32 "
                 "{%0,%1,%2,%3}, {%4,%5,%6,%7}, {%8,%9}, {%0,%1,%2,%3};"
                 : "+f"(d[0]), "+f"(d[1]), "+f"(d[2]), "+f"(d[3])
                 : "r"(a[0]), "r"(a[1]), "r"(a[2]), "r"(a[3]), "r"(b0), "r"(b1));
}
#define CP_ASYNC16(s, g) \
    asm volatile("cp.async.cg.shared.global [%0], [%1], 16;" :: "r"(s), "l"(g))
#define CP_COMMIT() asm volatile("cp.async.commit_group;" ::: "memory")
#define CP_WAIT1()  asm volatile("cp.async.wait_group 1;" ::: "memory")
#define CP_WAIT0()  asm volatile("cp.async.wait_group 0;" ::: "memory")
#define BAR_GRP(g)  asm volatile("bar.sync %0, 256;" :: "r"((g) + 1) : "memory")

__device__ __forceinline__ unsigned pk_f16(float a, float b) {
    __half2 h = __floats2half2_rn(a, b);
    return *(unsigned*)&h;
}

// ---------------------------------------------------------------------------
// Transpose: W [K][N] fp32 -> T [N][K] fp16
// ---------------------------------------------------------------------------
__global__ void __launch_bounds__(256)
prep_wt(const float* __restrict__ W, __half* __restrict__ T, int K, int N)
{
    __shared__ float tile[32][33];
    const int kb = blockIdx.y * 32, nb = blockIdx.x * 32;
    const int tx = threadIdx.x, ty = threadIdx.y;
    #pragma unroll
    for (int i = 0; i < 4; i++)
        tile[ty + i * 8][tx] = W[(size_t)(kb + ty + i * 8) * N + nb + tx];
    __syncthreads();
    #pragma unroll
    for (int i = 0; i < 4; i++)
        T[(size_t)(nb + ty + i * 8) * K + kb + tx] = __float2half_rn(tile[tx][ty + i * 8]);
}

// ---------------------------------------------------------------------------
// x fp32 -> fp16
// ---------------------------------------------------------------------------
__global__ void __launch_bounds__(256)
prep_x(const float* __restrict__ x, __half* __restrict__ xh, int n4)
{
    int i = blockIdx.x * 256 + threadIdx.x;
    if (i >= n4) return;
    float4 v = *(const float4*)&x[(size_t)i * 4];
    __half hbuf[4] = {__float2half_rn(v.x), __float2half_rn(v.y),
                      __float2half_rn(v.z), __float2half_rn(v.w)};
    *(uint2*)&xh[(size_t)i * 4] = *(uint2*)hbuf;
}

// ---------------------------------------------------------------------------
// fp16 tensor-core GEMM v3: C = A @ Bt^T + bias   (A,Bt fp16; C fp32)
// 512 threads = 16 warps: rb = wid&7 -> 16 M-rows; grp = wid>>3 -> 64 N-cols.
// CTA tile 128x128, K-chunks of 64. BOTH A and B staged in smem via cp.async
// (double buffered, 2x(16+16) KB); fragments via ldmatrix (was: 16 global
// LDG.32 per warp/chunk for A -> now 4 LDSM, no duplicated A traffic).
// ---------------------------------------------------------------------------
#define GAB_B   32768                 // B region base (A at 0)
#define GSTRIDE 16384                 // per-buffer stride within region
#define GSMEM_TOTAL 65536

__global__ void __launch_bounds__(512, 1)
bgemm_kernel(const __half* __restrict__ A, const __half* __restrict__ Bt,
             float* __restrict__ C, int M, int N, int K,
             const float* __restrict__ bias)
{
    extern __shared__ char smem[];
    const unsigned sb = smem_u32(smem);
    const int tid = threadIdx.x, wid = tid >> 5, lane = tid & 31;
    const int g = lane >> 2, t4 = lane & 3;
    const int rb = wid & 7, grp = wid >> 3;
    const int bm = blockIdx.y * 128, bn = blockIdx.x * 128;
    const int mrow = lane & 7, m_hi = (lane >> 3) & 1, m_k = (lane >> 4) & 1;

    float Cf[8][4];
    #pragma unroll
    for (int j = 0; j < 8; j++)
        #pragma unroll
        for (int r = 0; r < 4; r++) Cf[j][r] = 0.f;

    // A+B tile loader: each [128 rows][64 k] fp16 SW128; 1024 chunks per tile
    auto load_ab = [&](int buf, int k0) {
        const unsigned ab = sb + (unsigned)buf * GSTRIDE;
        const unsigned bb = sb + GAB_B + (unsigned)buf * GSTRIDE;
        #pragma unroll
        for (int i = 0; i < 2; i++) {
            int c = tid + i * 512;
            int row = c >> 3, cc = c & 7;
            unsigned sw = swz((unsigned)(c * 16));
            CP_ASYNC16(ab + sw, (const uint4*)(A  + (size_t)(bm + row) * K + k0) + cc);
            CP_ASYNC16(bb + sw, (const uint4*)(Bt + (size_t)(bn + row) * K + k0) + cc);
        }
    };

    load_ab(0, 0);
    CP_COMMIT();

    const int NKC = K >> 6;
    #pragma unroll 1
    for (int kc = 0; kc < NKC; kc++) {
        if (kc + 1 < NKC) { load_ab((kc + 1) & 1, (kc + 1) * 64); CP_COMMIT(); CP_WAIT1(); }
        else              { CP_WAIT0(); }
        __syncthreads();

        const unsigned ta = sb + (unsigned)(kc & 1) * GSTRIDE;
        const unsigned tb = sb + GAB_B + (unsigned)(kc & 1) * GSTRIDE;

        // A fragments via ldmatrix (4 LDSM; x4 matrix order == a0..a3 layout)
        unsigned Af[4][4];
        #pragma unroll
        for (int s = 0; s < 4; s++)
            ldmx4(Af[s][0], Af[s][1], Af[s][2], Af[s][3],
                  ta + swz((unsigned)((rb * 16 + m_hi * 8 + mrow) * 128 + s * 32 + m_k * 16)));

        #pragma unroll
        for (int s = 0; s < 4; s++)
            #pragma unroll
            for (int np = 0; np < 4; np++) {
                int n = grp * 64 + np * 16 + m_hi * 8 + mrow;
                unsigned addr = tb + swz((unsigned)(n * 128 + s * 32 + m_k * 16));
                unsigned b0, b1, b2, b3;
                ldmx4(b0, b1, b2, b3, addr);
                mma16816h(Cf[np * 2],     Af[s], b0, b2);
                mma16816h(Cf[np * 2 + 1], Af[s], b1, b3);
            }
        __syncthreads();
    }

    const int row0 = bm + rb * 16 + g;
    #pragma unroll
    for (int j = 0; j < 8; j++) {
        const int col = bn + grp * 64 + j * 8 + t4 * 2;
        float b0 = 0.f, b1 = 0.f;
        if (bias) { float2 bv = *(const float2*)&bias[col]; b0 = bv.x; b1 = bv.y; }
        *(float2*)&C[(size_t)row0 * N + col]       = make_float2(Cf[j][0] + b0, Cf[j][1] + b1);
        *(float2*)&C[(size_t)(row0 + 8) * N + col] = make_float2(Cf[j][2] + b0, Cf[j][3] + b1);
    }
}

// ---------------------------------------------------------------------------
// Preps: K single fp16 (vectorized), V^T single fp16 (smem transpose)
// ---------------------------------------------------------------------------
__global__ void __launch_bounds__(256)
prep_k(const float* __restrict__ qkv)
{
    int i = blockIdx.x * 256 + threadIdx.x;            // [h][key][d4]
    int h = i / (N_TOK * 16);
    int rem = i % (N_TOK * 16);
    int key = rem / 16, d4 = rem % 16;
    float4 v = *(const float4*)&qkv[(size_t)key * (3 * DIM) + DIM + h * HD + d4 * 4];
    __half hbuf[4] = {__float2half_rn(v.x), __float2half_rn(v.y),
                      __float2half_rn(v.z), __float2half_rn(v.w)};
    *(uint2*)&g_Khi[(size_t)h * HE + (size_t)key * HD + d4 * 4] = *(uint2*)hbuf;
}

__global__ void __launch_bounds__(256)
prep_vt(const float* __restrict__ qkv)
{
    __shared__ float tile[32][33];
    const int kb = blockIdx.x * 32;        // key block
    const int db = blockIdx.y * 32;        // head-dim block
    const int h  = blockIdx.z;
    const int tx = threadIdx.x, ty = threadIdx.y;
    #pragma unroll
    for (int i = 0; i < 4; i++)
        tile[ty + i * 8][tx] = qkv[(size_t)(kb + ty + i * 8) * (3 * DIM) + 2 * DIM + h * HD + db + tx];
    __syncthreads();
    #pragma unroll
    for (int i = 0; i < 4; i++) {
        float v = tile[tx][ty + i * 8];
        g_Vhi[(size_t)h * HE + (size_t)(db + ty + i * 8) * N_TOK + kb + tx] = __float2half_rn(v);
    }
}

// ---------------------------------------------------------------------------
// mma.sync flash attention v6 (all-fp16; decoupled groups) — unchanged
// ---------------------------------------------------------------------------
#define AK_HI 0
#define AV_HI 8192
#define ABUF  16384
#define AGRP  32768
#define SMEM_TOTAL (2 * AGRP)

__device__ __forceinline__ void load_half_tile(
    unsigned sb, int grp, int buf, int h, int kk0, int gtid,
    const __half* __restrict__ Khi, const __half* __restrict__ Vhi)
{
    const unsigned base = sb + (unsigned)grp * AGRP + (unsigned)buf * ABUF;
    const int key0 = kk0 + grp * 64;
    #pragma unroll
    for (int i = 0; i < 2; i++) {
        int c = gtid + i * 256;                      // 0..511 16B chunks
        int row = c >> 3, cc = c & 7;
        unsigned sw = swz((unsigned)(c * 16));
        const size_t ko = (size_t)h * HE + (size_t)(key0 + row) * HD;
        CP_ASYNC16(base + AK_HI + sw, (const uint4*)(Khi + ko) + cc);
        const size_t vo = (size_t)h * HE + (size_t)row * N_TOK + key0;
        CP_ASYNC16(base + AV_HI + sw, (const uint4*)(Vhi + vo) + cc);
    }
}

__global__ void __launch_bounds__(512, 1)
attn_mma_kernel(const float* __restrict__ qkv,
                const __half* __restrict__ Khi, const __half* __restrict__ Vhi,
                __half* __restrict__ outh)
{
    extern __shared__ char smem[];
    const unsigned sb = smem_u32(smem);
    const int tid = threadIdx.x, wid = tid >> 5, lane = tid & 31;
    const int g = lane >> 2, t4 = lane & 3;
    const int rb = wid & 7, grp = wid >> 3;
    const int gtid = tid & 255;
    const int h = blockIdx.y, q0 = blockIdx.x * 128;
    const int mrow = lane & 7, m_hi = (lane >> 3) & 1, m_k = (lane >> 4) & 1;

    // ---- Q fragments (UNscaled, fp16 single) from fp32 qkv ----
    unsigned Qf[4][4];
    {
        const int qrow0 = q0 + rb * 16;
        #pragma unroll
        for (int s = 0; s < 4; s++)
            #pragma unroll
            for (int r = 0; r < 4; r++) {
                int row = qrow0 + g + (r & 1) * 8;
                int col = s * 16 + (r >> 1) * 8 + t4 * 2;
                float2 v = *(const float2*)&qkv[(size_t)row * (3 * DIM) + h * HD + col];
                Qf[s][r] = pk_f16(v.x, v.y);
            }
    }

    float O[8][4];
    #pragma unroll
    for (int j = 0; j < 8; j++)
        #pragma unroll
        for (int r = 0; r < 4; r++) O[j][r] = 0.f;
    float lg = 0.f, lg8 = 0.f;

    load_half_tile(sb, grp, 0, h, 0, gtid, Khi, Vhi);
    CP_COMMIT();

    #pragma unroll 1
    for (int t = 0; t < NT; t++) {
        const int buf = t & 1;
        const unsigned tb = sb + (unsigned)grp * AGRP + (unsigned)buf * ABUF;

        if (t + 1 < NT) {
            load_half_tile(sb, grp, buf ^ 1, h, (t + 1) * 128, gtid, Khi, Vhi);
            CP_COMMIT();
            CP_WAIT1();
        } else {
            CP_WAIT0();
        }
        BAR_GRP(grp);

        // ---- S = Q*K -> P (fp16) ----
        unsigned Phi[4][4];
        #pragma unroll
        for (int half = 0; half < 2; half++) {
            float S[4][4];
            #pragma unroll
            for (int j = 0; j < 4; j++)
                #pragma unroll
                for (int r = 0; r < 4; r++) S[j][r] = 0.f;

            #pragma unroll
            for (int s = 0; s < 4; s++)
                #pragma unroll
                for (int npl = 0; npl < 2; npl++) {
                    int keyl = (half * 2 + npl) * 16 + m_hi * 8 + mrow;
                    unsigned b0, b1, b2, b3;
                    ldmx4(b0, b1, b2, b3,
                          tb + AK_HI + swz((unsigned)(keyl * 128 + s * 32 + m_k * 16)));
                    mma16816h(S[npl * 2],     Qf[s], b0, b2);
                    mma16816h(S[npl * 2 + 1], Qf[s], b1, b3);
                }

            #pragma unroll
            for (int j = 0; j < 4; j++) {
                float p0 = __expf(S[j][0] * 0.125f), p1 = __expf(S[j][1] * 0.125f);
                float p2 = __expf(S[j][2] * 0.125f), p3 = __expf(S[j][3] * 0.125f);
                lg  += p0 + p1;
                lg8 += p2 + p3;
                int np = half * 2 + (j >> 1), o = (j & 1) * 2;
                Phi[np][o]     = pk_f16(p0, p1);
                Phi[np][o + 1] = pk_f16(p2, p3);
            }
        }

        // ---- O += P*V (this group's 64-key half) ----
        #pragma unroll
        for (int s = 0; s < 4; s++) {
            int keybyte = s * 32 + m_k * 16;
            #pragma unroll
            for (int np = 0; np < 4; np++) {
                int hd = np * 16 + m_hi * 8 + mrow;
                unsigned b0, b1, b2, b3;
                ldmx4(b0, b1, b2, b3, tb + AV_HI + swz((unsigned)(hd * 128 + keybyte)));
                mma16816h(O[np * 2],     Phi[s], b0, b2);
                mma16816h(O[np * 2 + 1], Phi[s], b1, b3);
            }
        }
        BAR_GRP(grp);
    }

    // ---- cross-group reduction of O and l, normalize, store fp16 ----
    float l0 = lg;  l0 += __shfl_xor_sync(0xffffffff, l0, 1); l0 += __shfl_xor_sync(0xffffffff, l0, 2);
    float l1 = lg8; l1 += __shfl_xor_sync(0xffffffff, l1, 1); l1 += __shfl_xor_sync(0xffffffff, l1, 2);

    __syncthreads();
    float* Ox = (float*)smem;              // [128 rows][64 cols] = 32KB
    float* Lx = (float*)(smem + 32768);    // [128]
    if (grp == 1) {
        #pragma unroll
        for (int j = 0; j < 8; j++) {
            const int col = j * 8 + t4 * 2;
            *(float2*)&Ox[(rb * 16 + g) * 64 + col]     = make_float2(O[j][0], O[j][1]);
            *(float2*)&Ox[(rb * 16 + g + 8) * 64 + col] = make_float2(O[j][2], O[j][3]);
        }
        if (t4 == 0) { Lx[rb * 16 + g] = l0; Lx[rb * 16 + g + 8] = l1; }
    }
    __syncthreads();
    if (grp == 0) {
        const float inv0 = 1.f / (l0 + Lx[rb * 16 + g]);
        const float inv1 = 1.f / (l1 + Lx[rb * 16 + g + 8]);
        const int row0 = q0 + rb * 16 + g;
        #pragma unroll
        for (int j = 0; j < 8; j++) {
            const int col = j * 8 + t4 * 2;
            float2 a0 = *(float2*)&Ox[(rb * 16 + g) * 64 + col];
            float2 a1 = *(float2*)&Ox[(rb * 16 + g + 8) * 64 + col];
            *(unsigned*)&outh[(size_t)row0 * DIM + h * HD + col] =
                pk_f16((O[j][0] + a0.x) * inv0, (O[j][1] + a0.y) * inv0);
            *(unsigned*)&outh[(size_t)(row0 + 8) * DIM + h * HD + col] =
                pk_f16((O[j][2] + a1.x) * inv1, (O[j][3] + a1.y) * inv1);
        }
    }
}

// ---------------------------------------------------------------------------
extern "C" void kernel_launch(void* const* d_in, const int* in_sizes, int n_in,
                              void* d_out, int out_size)
{
    const float* x      = (const float*)d_in[0];
    const float* W_qkv  = (const float*)d_in[1];
    const float* W_proj = (const float*)d_in[2];
    const float* b_proj = (const float*)d_in[3];
    float* out = (float*)d_out;

    float* qkv;   cudaGetSymbolAddress((void**)&qkv,   g_qkv);
    __half *xh, *attnh, *kh, *vh, *wqt, *wpt;
    cudaGetSymbolAddress((void**)&xh,    g_xh);
    cudaGetSymbolAddress((void**)&attnh, g_attnh);
    cudaGetSymbolAddress((void**)&kh,  g_Khi);
    cudaGetSymbolAddress((void**)&vh,  g_Vhi);
    cudaGetSymbolAddress((void**)&wqt, g_Wqt);
    cudaGetSymbolAddress((void**)&wpt, g_Wpt);

    cudaFuncSetAttribute(attn_mma_kernel, cudaFuncAttributeMaxDynamicSharedMemorySize, SMEM_TOTAL);
    cudaFuncSetAttribute(bgemm_kernel,    cudaFuncAttributeMaxDynamicSharedMemorySize, GSMEM_TOTAL);

    // 0) weight transpose (fp16) and x -> fp16
    prep_wt<<<dim3(3 * DIM / 32, DIM / 32), dim3(32, 8)>>>(W_qkv,  wqt, DIM, 3 * DIM);
    prep_wt<<<dim3(DIM / 32,     DIM / 32), dim3(32, 8)>>>(W_proj, wpt, DIM, DIM);
    prep_x<<<(N_TOK * DIM / 4 + 255) / 256, 256>>>(x, xh, N_TOK * DIM / 4);

    // 1) qkv = xh @ W_qkv  (fp16, A+B via smem/ldmatrix)
    bgemm_kernel<<<dim3(3 * DIM / 128, N_TOK / 128), 512, GSMEM_TOTAL>>>(
        xh, wqt, qkv, N_TOK, 3 * DIM, DIM, nullptr);

    // 2) convert K and V^T (single fp16)
    prep_k <<<HEADS * N_TOK * 16 / 256, 256>>>(qkv);
    prep_vt<<<dim3(N_TOK / 32, HD / 32, HEADS), dim3(32, 8)>>>(qkv);

    // 3) fp16 flash attention -> fp16 output
    {
        dim3 grid(N_TOK / 128, HEADS);
        attn_mma_kernel<<<grid, 512, SMEM_TOTAL>>>(qkv, kh, vh, attnh);
    }

    // 4) out = attnh @ W_proj + b  (fp16)
    bgemm_kernel<<<dim3(DIM / 128, N_TOK / 128), 512, GSMEM_TOTAL>>>(
        attnh, wpt, out, N_TOK, DIM, DIM, b_proj);
}